// round 11
// baseline (speedup 1.0000x reference)
#include <cuda_runtime.h>
#include <cuda_bf16.h>
#include <cstdint>
#include <math.h>

// Problem constants: b=2, t=8, L=1024, c=256, H=8, D=32
#define M_ROWS 16384
#define CDIM   256
#define NHEAD  8
#define DHEAD  32
#define LSEQ   1024
#define BTH    128

// 1/sqrt(32) folded into Q at projection epilogue
#define QSCALE 0.17677669529663687f

// Scratch (device globals)
__device__ __nv_bfloat16 g_x16[12582912];  // q,k,v inputs in bf16
__device__ __nv_bfloat16 g_w16[262144];    // Wq,Wk,Wv,Wm in bf16
__device__ __nv_bfloat16 g_q16[4194304];   // [bth, l, d]  (pre-scaled)
__device__ __nv_bfloat16 g_k16[4194304];   // [bth, l, d]
__device__ __nv_bfloat16 g_v16[4194304];   // [bth, l, d]
__device__ __nv_bfloat16 g_att16[4194304]; // [bt, l, c]

// ---------------------------------------------------------------------------
__device__ __forceinline__ uint32_t smem_u32(const void* p) {
    uint32_t a;
    asm("{ .reg .u64 t; cvta.to.shared.u64 t, %1; cvt.u32.u64 %0, t; }" : "=r"(a) : "l"(p));
    return a;
}

#define LDSM_X4(r0, r1, r2, r3, addr) \
    asm volatile("ldmatrix.sync.aligned.m8n8.x4.shared.b16 {%0,%1,%2,%3}, [%4];" \
                 : "=r"(r0), "=r"(r1), "=r"(r2), "=r"(r3) : "r"(addr))
#define LDSM_X4T(r0, r1, r2, r3, addr) \
    asm volatile("ldmatrix.sync.aligned.m8n8.x4.trans.shared.b16 {%0,%1,%2,%3}, [%4];" \
                 : "=r"(r0), "=r"(r1), "=r"(r2), "=r"(r3) : "r"(addr))

#define MMA_BF16(c0, c1, c2, c3, a0, a1, a2, a3, b0, b1) \
    asm volatile("mma.sync.aligned.m16n8k16.row.col.f32.bf16.bf16.f32 " \
                 "{%0,%1,%2,%3}, {%4,%5,%6,%7}, {%8,%9}, {%0,%1,%2,%3};" \
                 : "+f"(c0), "+f"(c1), "+f"(c2), "+f"(c3) \
                 : "r"(a0), "r"(a1), "r"(a2), "r"(a3), "r"(b0), "r"(b1))

#define CVT_BF16X2(r, hi, lo) \
    asm("cvt.rn.bf16x2.f32 %0, %1, %2;" : "=r"(r) : "f"(hi), "f"(lo))

#define HFMA2_BF(d, a, b, cc) \
    asm("fma.rn.bf16x2 %0, %1, %2, %3;" : "=r"(d) : "r"(a), "r"(b), "r"(cc))

#define CP16(dst, src) \
    asm volatile("cp.async.cg.shared.global [%0], [%1], 16;" :: "r"(dst), "l"(src))
#define CP_COMMIT() asm volatile("cp.async.commit_group;")
#define CP_WAIT(n)  asm volatile("cp.async.wait_group %0;" :: "n"(n))

// bf16x2 constants for exp poly
#define ONES_BF16X2  0x3F803F80u
#define HALF_BF16X2  0x3F003F00u
#define SIXTH_BF16X2 0x3E2B3E2Bu

__device__ __forceinline__ uint32_t exp_bf16x2(uint32_t x) {
    uint32_t t;
    HFMA2_BF(t, x, SIXTH_BF16X2, HALF_BF16X2);
    HFMA2_BF(t, x, t, ONES_BF16X2);
    HFMA2_BF(t, x, t, ONES_BF16X2);
    return t;
}

// ---------------------------------------------------------------------------
// Kernel 0: fp32 -> bf16 conversion of q,k,v and the 4 weight matrices.
// ---------------------------------------------------------------------------
#define XQ 1048576
#define WQ 16384
__global__ __launch_bounds__(256) void convert_kernel(
    const float* __restrict__ q, const float* __restrict__ k, const float* __restrict__ v,
    const float* __restrict__ Wq, const float* __restrict__ Wk,
    const float* __restrict__ Wv, const float* __restrict__ Wm)
{
    int idx = blockIdx.x * 256 + threadIdx.x;
    const float* src;
    uint2* dst;
    int local;
    if (idx < 3 * XQ) {
        int sel = idx / XQ;
        local = idx - sel * XQ;
        src = (sel == 0) ? q : (sel == 1) ? k : v;
        dst = (uint2*)g_x16 + idx;
    } else {
        int wi = idx - 3 * XQ;
        int sel = wi / WQ;
        local = wi - sel * WQ;
        src = (sel == 0) ? Wq : (sel == 1) ? Wk : (sel == 2) ? Wv : Wm;
        dst = (uint2*)g_w16 + wi;
    }
    float4 vv = ((const float4*)src)[local];
    uint32_t lo, hi;
    CVT_BF16X2(lo, vv.y, vv.x);
    CVT_BF16X2(hi, vv.w, vv.z);
    *dst = make_uint2(lo, hi);
}

// ---------------------------------------------------------------------------
// Kernel 1: merged q/k/v bf16 GEMM projection.
// 3-stage cp.async pipeline (prefetch distance 2), ONE barrier per chunk.
// ---------------------------------------------------------------------------
__global__ __launch_bounds__(256, 2) void qkv_proj_kernel(
    const float* __restrict__ bq, const float* __restrict__ bk,
    const float* __restrict__ bv)
{
    __shared__ __nv_bfloat16 Xs[3][128][40];
    __shared__ __nv_bfloat16 Ws[3][128][40];

    const int sel = blockIdx.z;
    const __nv_bfloat16* X = g_x16 + (size_t)sel * 4194304;
    const __nv_bfloat16* W = g_w16 + sel * 65536;
    const float* bias = (sel == 0) ? bq : (sel == 1) ? bk : bv;
    const float extra = (sel == 0) ? QSCALE : 1.0f;
    __nv_bfloat16* Out = (sel == 0) ? g_q16 : (sel == 1) ? g_k16 : g_v16;

    const int tid = threadIdx.x;
    const int w = tid >> 5, lane = tid & 31;
    const int wm = w >> 1, wn = w & 1;
    const int groupID = lane >> 2, tid4 = lane & 3;
    const int rowBase = blockIdx.x * 128;
    const int colBase = blockIdx.y * 128;

    const int lr0 = tid >> 2, lp0 = tid & 3;
    const int lr1 = lr0 + 64;

    float c[2][8][4];
#pragma unroll
    for (int mt = 0; mt < 2; ++mt)
#pragma unroll
        for (int nt = 0; nt < 8; ++nt)
#pragma unroll
            for (int i = 0; i < 4; ++i) c[mt][nt][i] = 0.f;

#pragma unroll
    for (int pc = 0; pc < 2; ++pc) {
        int ko = pc * 32;
        CP16(smem_u32(&Xs[pc][lr0][lp0 * 8]), X + (size_t)(rowBase + lr0) * CDIM + ko + lp0 * 8);
        CP16(smem_u32(&Xs[pc][lr1][lp0 * 8]), X + (size_t)(rowBase + lr1) * CDIM + ko + lp0 * 8);
        CP16(smem_u32(&Ws[pc][lr0][lp0 * 8]), W + (size_t)(colBase + lr0) * CDIM + ko + lp0 * 8);
        CP16(smem_u32(&Ws[pc][lr1][lp0 * 8]), W + (size_t)(colBase + lr1) * CDIM + ko + lp0 * 8);
        CP_COMMIT();
    }

#pragma unroll
    for (int kt = 0; kt < 8; ++kt) {
        const int cb = kt % 3;
        if (kt < 7) { CP_WAIT(1); } else { CP_WAIT(0); }
        __syncthreads();
        if (kt < 6) {
            const int nb = (kt + 2) % 3;
            int ko = (kt + 2) * 32;
            CP16(smem_u32(&Xs[nb][lr0][lp0 * 8]), X + (size_t)(rowBase + lr0) * CDIM + ko + lp0 * 8);
            CP16(smem_u32(&Xs[nb][lr1][lp0 * 8]), X + (size_t)(rowBase + lr1) * CDIM + ko + lp0 * 8);
            CP16(smem_u32(&Ws[nb][lr0][lp0 * 8]), W + (size_t)(colBase + lr0) * CDIM + ko + lp0 * 8);
            CP16(smem_u32(&Ws[nb][lr1][lp0 * 8]), W + (size_t)(colBase + lr1) * CDIM + ko + lp0 * 8);
            CP_COMMIT();
        }

        uint32_t a[2][2][4];
#pragma unroll
        for (int mt = 0; mt < 2; ++mt)
#pragma unroll
            for (int ks = 0; ks < 2; ++ks) {
                uint32_t addr = smem_u32(
                    &Xs[cb][wm * 32 + mt * 16 + (lane & 7) + ((lane & 8) ? 8 : 0)]
                       [ks * 16 + ((lane & 16) ? 8 : 0)]);
                LDSM_X4(a[mt][ks][0], a[mt][ks][1], a[mt][ks][2], a[mt][ks][3], addr);
            }
#pragma unroll
        for (int nt = 0; nt < 8; ++nt) {
            uint32_t b[4];
            uint32_t addr = smem_u32(&Ws[cb][wn * 64 + nt * 8 + (lane & 7)][(lane >> 3) * 8]);
            LDSM_X4(b[0], b[1], b[2], b[3], addr);
#pragma unroll
            for (int mt = 0; mt < 2; ++mt) {
                MMA_BF16(c[mt][nt][0], c[mt][nt][1], c[mt][nt][2], c[mt][nt][3],
                         a[mt][0][0], a[mt][0][1], a[mt][0][2], a[mt][0][3], b[0], b[1]);
                MMA_BF16(c[mt][nt][0], c[mt][nt][1], c[mt][nt][2], c[mt][nt][3],
                         a[mt][1][0], a[mt][1][1], a[mt][1][2], a[mt][1][3], b[2], b[3]);
            }
        }
    }

    float2 bj[8];
#pragma unroll
    for (int nt = 0; nt < 8; ++nt)
        bj[nt] = *(const float2*)(bias + colBase + wn * 64 + nt * 8 + tid4 * 2);
#pragma unroll
    for (int mt = 0; mt < 2; ++mt)
#pragma unroll
        for (int nt = 0; nt < 8; ++nt) {
            c[mt][nt][0] += bj[nt].x; c[mt][nt][1] += bj[nt].y;
            c[mt][nt][2] += bj[nt].x; c[mt][nt][3] += bj[nt].y;
        }

#pragma unroll
    for (int mt = 0; mt < 2; ++mt) {
        float ss[2][2];
        ss[0][0] = ss[0][1] = ss[1][0] = ss[1][1] = 0.f;
#pragma unroll
        for (int nt = 0; nt < 8; ++nt) {
            int hd = nt >> 2;
            ss[0][hd] += c[mt][nt][0] * c[mt][nt][0] + c[mt][nt][1] * c[mt][nt][1];
            ss[1][hd] += c[mt][nt][2] * c[mt][nt][2] + c[mt][nt][3] * c[mt][nt][3];
        }
        float scl[2][2];
#pragma unroll
        for (int rh = 0; rh < 2; ++rh)
#pragma unroll
            for (int hd = 0; hd < 2; ++hd) {
                float s = ss[rh][hd];
                s += __shfl_xor_sync(0xffffffffu, s, 1);
                s += __shfl_xor_sync(0xffffffffu, s, 2);
                scl[rh][hd] = extra / fmaxf(sqrtf(s), 1e-12f);
            }
#pragma unroll
        for (int rh = 0; rh < 2; ++rh) {
            int grow = rowBase + wm * 32 + mt * 16 + groupID + rh * 8;
            int bt = grow >> 10, l = grow & 1023;
#pragma unroll
            for (int nt = 0; nt < 8; ++nt) {
                int j = colBase + wn * 64 + nt * 8 + tid4 * 2;
                int h = j >> 5, dd = j & 31;
                float sc = scl[rh][nt >> 2];
                uint32_t pk;
                CVT_BF16X2(pk, c[mt][nt][rh * 2 + 1] * sc, c[mt][nt][rh * 2 + 0] * sc);
                *(uint32_t*)(Out + (((size_t)bt * NHEAD + h) * LSEQ + l) * DHEAD + dd) = pk;
            }
        }
    }
}

// ---------------------------------------------------------------------------
// Kernel 2: bf16 flash attention. 256 threads, 8 warps x m32 = 256 q rows
// per CTA (grid 4 x 128). K/V double-buffered (40KB -> 2 CTAs/SM =
// 4 warps/SMSP). Row sums on tensor pipe; exp as packed-bf16x2 poly.
// ---------------------------------------------------------------------------
__global__ __launch_bounds__(256, 2) void attn_mma_kernel()
{
    __shared__ __nv_bfloat16 sK[2][128][40];
    __shared__ __nv_bfloat16 sV[2][128][40];

    const int tid = threadIdx.x;
    const int w = tid >> 5, lane = tid & 31;
    const int groupID = lane >> 2, tid4 = lane & 3;
    const int bth = blockIdx.y, qt = blockIdx.x;

    const char* Qg = (const char*)(g_q16 + ((size_t)bth * LSEQ + qt * 256) * DHEAD);
    const char* Kg = (const char*)(g_k16 + (size_t)bth * LSEQ * DHEAD);
    const char* Vg = (const char*)(g_v16 + (size_t)bth * LSEQ * DHEAD);

    // Stage Q (256 rows x 64B): rows 0-127 -> sK[0], rows 128-255 -> sV[0]
#pragma unroll
    for (int i = 0; i < 4; ++i) {
        int f = tid + i * 256;
        int row = f >> 2, part = f & 3;
        __nv_bfloat16* dst = (row < 128) ? &sK[0][row][part * 8]
                                         : &sV[0][row - 128][part * 8];
        *(float4*)dst = *(const float4*)(Qg + (size_t)row * 64 + part * 16);
    }
    __syncthreads();

    // Q fragments: warp w owns rows [w*32, w*32+32)
    uint32_t qa[2][2][4];
#pragma unroll
    for (int mt = 0; mt < 2; ++mt)
#pragma unroll
        for (int kc = 0; kc < 2; ++kc) {
            int grow = w * 32 + mt * 16 + (lane & 7) + ((lane & 8) ? 8 : 0);
            int col = kc * 16 + ((lane & 16) ? 8 : 0);
            const __nv_bfloat16* src = (grow < 128) ? &sK[0][grow][col]
                                                    : &sV[0][grow - 128][col];
            uint32_t addr = smem_u32(src);
            LDSM_X4(qa[mt][kc][0], qa[mt][kc][1], qa[mt][kc][2], qa[mt][kc][3], addr);
        }
    __syncthreads();

    // prologue: K/V tile 0 -> buf 0
#pragma unroll
    for (int i = 0; i < 2; ++i) {
        int f = tid + i * 256;
        int row = f >> 2, part = f & 3;
        CP16(smem_u32(&sK[0][row][part * 8]), Kg + (size_t)row * 64 + part * 16);
        CP16(smem_u32(&sV[0][row][part * 8]), Vg + (size_t)row * 64 + part * 16);
    }
    CP_COMMIT();

    float o[2][4][4];
    float su[2][4];
#pragma unroll
    for (int mt = 0; mt < 2; ++mt) {
#pragma unroll
        for (int dn = 0; dn < 4; ++dn)
#pragma unroll
            for (int i = 0; i < 4; ++i) o[mt][dn][i] = 0.f;
#pragma unroll
        for (int i = 0; i < 4; ++i) su[mt][i] = 0.f;
    }

    for (int kt = 0; kt < 8; ++kt) {
        const int cb = kt & 1;
        CP_WAIT(0);
        __syncthreads();
        if (kt < 7) {
            const int nb = (kt + 1) & 1;
            const char* Kt = Kg + (size_t)(kt + 1) * 128 * 64;
            const char* Vt = Vg + (size_t)(kt + 1) * 128 * 64;
#pragma unroll
            for (int i = 0; i < 2; ++i) {
                int f = tid + i * 256;
                int row = f >> 2, part = f & 3;
                CP16(smem_u32(&sK[nb][row][part * 8]), Kt + (size_t)row * 64 + part * 16);
                CP16(smem_u32(&sV[nb][row][part * 8]), Vt + (size_t)row * 64 + part * 16);
            }
            CP_COMMIT();
        }

#pragma unroll
        for (int half = 0; half < 2; ++half) {
#pragma unroll
            for (int kc = 0; kc < 4; ++kc) {
                uint32_t pa[2][4];
#pragma unroll
                for (int sub = 0; sub < 2; ++sub) {
                    int nbk = half * 64 + (kc * 2 + sub) * 8;
                    uint32_t kb[4];
                    uint32_t addr = smem_u32(&sK[cb][nbk + (lane & 7)][(lane >> 3) * 8]);
                    LDSM_X4(kb[0], kb[1], kb[2], kb[3], addr);
#pragma unroll
                    for (int mt = 0; mt < 2; ++mt) {
                        float s0 = 0.f, s1 = 0.f, s2 = 0.f, s3 = 0.f;
                        MMA_BF16(s0, s1, s2, s3,
                                 qa[mt][0][0], qa[mt][0][1], qa[mt][0][2], qa[mt][0][3],
                                 kb[0], kb[1]);
                        MMA_BF16(s0, s1, s2, s3,
                                 qa[mt][1][0], qa[mt][1][1], qa[mt][1][2], qa[mt][1][3],
                                 kb[2], kb[3]);
                        uint32_t x01, x23;
                        CVT_BF16X2(x01, s1, s0);
                        CVT_BF16X2(x23, s3, s2);
                        pa[mt][sub * 2 + 0] = exp_bf16x2(x01);
                        pa[mt][sub * 2 + 1] = exp_bf16x2(x23);
                    }
                }
#pragma unroll
                for (int dp = 0; dp < 2; ++dp) {
                    uint32_t vb[4];
                    uint32_t addr = smem_u32(
                        &sV[cb][half * 64 + kc * 16 + (lane & 15)]
                           [dp * 16 + ((lane & 16) ? 8 : 0)]);
                    LDSM_X4T(vb[0], vb[1], vb[2], vb[3], addr);
#pragma unroll
                    for (int mt = 0; mt < 2; ++mt) {
                        MMA_BF16(o[mt][2 * dp][0], o[mt][2 * dp][1],
                                 o[mt][2 * dp][2], o[mt][2 * dp][3],
                                 pa[mt][0], pa[mt][1], pa[mt][2], pa[mt][3],
                                 vb[0], vb[1]);
                        MMA_BF16(o[mt][2 * dp + 1][0], o[mt][2 * dp + 1][1],
                                 o[mt][2 * dp + 1][2], o[mt][2 * dp + 1][3],
                                 pa[mt][0], pa[mt][1], pa[mt][2], pa[mt][3],
                                 vb[2], vb[3]);
                    }
                }
#pragma unroll
                for (int mt = 0; mt < 2; ++mt)
                    MMA_BF16(su[mt][0], su[mt][1], su[mt][2], su[mt][3],
                             pa[mt][0], pa[mt][1], pa[mt][2], pa[mt][3],
                             ONES_BF16X2, ONES_BF16X2);
            }
        }
    }

    const int bt = bth >> 3, h = bth & 7;
#pragma unroll
    for (int mt = 0; mt < 2; ++mt) {
        const float inv0 = 1.f / su[mt][0];
        const float inv1 = 1.f / su[mt][2];
        const int l0 = qt * 256 + w * 32 + mt * 16 + groupID;
#pragma unroll
        for (int dn = 0; dn < 4; ++dn) {
            int col = h * DHEAD + dn * 8 + tid4 * 2;
            uint32_t pk0, pk1;
            CVT_BF16X2(pk0, o[mt][dn][1] * inv0, o[mt][dn][0] * inv0);
            CVT_BF16X2(pk1, o[mt][dn][3] * inv1, o[mt][dn][2] * inv1);
            *(uint32_t*)(g_att16 + ((size_t)bt * LSEQ + l0) * CDIM + col) = pk0;
            *(uint32_t*)(g_att16 + ((size_t)bt * LSEQ + l0 + 8) * CDIM + col) = pk1;
        }
    }
}

// ---------------------------------------------------------------------------
// Kernel 3: Out = g_att16 @ Wm^T + bm + shortcut (fp32 out).
// 64x128 tiles -> 512 CTAs. 8 warps as 2(m) x 4(n), warp tile 32x32.
// 3-stage cp.async pipeline. Loader: X 64x32 = 256 chunks (1/thread),
// W 128x32 = 512 chunks (2/thread).
// ---------------------------------------------------------------------------
__global__ __launch_bounds__(256, 2) void final_bf16_kernel(
    const float* __restrict__ bias, const float* __restrict__ shortcut,
    float* __restrict__ Out)
{
    __shared__ __nv_bfloat16 Xs[3][64][40];
    __shared__ __nv_bfloat16 Ws[3][128][40];

    const __nv_bfloat16* X = g_att16;
    const __nv_bfloat16* W = g_w16 + 3 * 65536;

    const int tid = threadIdx.x;
    const int w = tid >> 5, lane = tid & 31;
    const int wm = w >> 2, wn = w & 3;
    const int groupID = lane >> 2, tid4 = lane & 3;
    const int rowBase = blockIdx.x * 64;
    const int colBase = blockIdx.y * 128;

    const int xr = tid >> 2, xp = tid & 3;     // X rows 0..63, 4 parts/row
    const int wr0 = tid >> 2, wr1 = wr0 + 64;  // W rows 0..127, 4 parts/row
    const int wp = tid & 3;

    float c[2][4][4];
#pragma unroll
    for (int mt = 0; mt < 2; ++mt)
#pragma unroll
        for (int nt = 0; nt < 4; ++nt)
#pragma unroll
            for (int i = 0; i < 4; ++i) c[mt][nt][i] = 0.f;

#pragma unroll
    for (int pc = 0; pc < 2; ++pc) {
        int ko = pc * 32;
        CP16(smem_u32(&Xs[pc][xr][xp * 8]), X + (size_t)(rowBase + xr) * CDIM + ko + xp * 8);
        CP16(smem_u32(&Ws[pc][wr0][wp * 8]), W + (size_t)(colBase + wr0) * CDIM + ko + wp * 8);
        CP16(smem_u32(&Ws[pc][wr1][wp * 8]), W + (size_t)(colBase + wr1) * CDIM + ko + wp * 8);
        CP_COMMIT();
    }

#pragma unroll
    for (int kt = 0; kt < 8; ++kt) {
        const int cb = kt % 3;
        if (kt < 7) { CP_WAIT(1); } else { CP_WAIT(0); }
        __syncthreads();
        if (kt < 6) {
            const int nb = (kt + 2) % 3;
            int ko = (kt + 2) * 32;
            CP16(smem_u32(&Xs[nb][xr][xp * 8]), X + (size_t)(rowBase + xr) * CDIM + ko + xp * 8);
            CP16(smem_u32(&Ws[nb][wr0][wp * 8]), W + (size_t)(colBase + wr0) * CDIM + ko + wp * 8);
            CP16(smem_u32(&Ws[nb][wr1][wp * 8]), W + (size_t)(colBase + wr1) * CDIM + ko + wp * 8);
            CP_COMMIT();
        }

        uint32_t a[2][2][4];
#pragma unroll
        for (int mt = 0; mt < 2; ++mt)
#pragma unroll
            for (int ks = 0; ks < 2; ++ks) {
                uint32_t addr = smem_u32(
                    &Xs[cb][wm * 32 + mt * 16 + (lane & 7) + ((lane & 8) ? 8 : 0)]
                       [ks * 16 + ((lane & 16) ? 8 : 0)]);
                LDSM_X4(a[mt][ks][0], a[mt][ks][1], a[mt][ks][2], a[mt][ks][3], addr);
            }
#pragma unroll
        for (int nt = 0; nt < 4; ++nt) {
            uint32_t b[4];
            uint32_t addr = smem_u32(&Ws[cb][wn * 32 + nt * 8 + (lane & 7)][(lane >> 3) * 8]);
            LDSM_X4(b[0], b[1], b[2], b[3], addr);
#pragma unroll
            for (int mt = 0; mt < 2; ++mt) {
                MMA_BF16(c[mt][nt][0], c[mt][nt][1], c[mt][nt][2], c[mt][nt][3],
                         a[mt][0][0], a[mt][0][1], a[mt][0][2], a[mt][0][3], b[0], b[1]);
                MMA_BF16(c[mt][nt][0], c[mt][nt][1], c[mt][nt][2], c[mt][nt][3],
                         a[mt][1][0], a[mt][1][1], a[mt][1][2], a[mt][1][3], b[2], b[3]);
            }
        }
    }

    float2 bj[4];
#pragma unroll
    for (int nt = 0; nt < 4; ++nt)
        bj[nt] = *(const float2*)(bias + colBase + wn * 32 + nt * 8 + tid4 * 2);

#pragma unroll
    for (int mt = 0; mt < 2; ++mt)
#pragma unroll
        for (int rh = 0; rh < 2; ++rh) {
            int grow = rowBase + wm * 32 + mt * 16 + groupID + rh * 8;
#pragma unroll
            for (int nt = 0; nt < 4; ++nt) {
                int j = colBase + wn * 32 + nt * 8 + tid4 * 2;
                size_t addr = (size_t)grow * CDIM + j;
                float2 sc = *(const float2*)(shortcut + addr);
                float2 ov;
                ov.x = c[mt][nt][rh * 2 + 0] + bj[nt].x + sc.x;
                ov.y = c[mt][nt][rh * 2 + 1] + bj[nt].y + sc.y;
                *(float2*)(Out + addr) = ov;
            }
        }
}

// ---------------------------------------------------------------------------
extern "C" void kernel_launch(void* const* d_in, const int* in_sizes, int n_in,
                              void* d_out, int out_size)
{
    const float* q  = (const float*)d_in[0];
    const float* k  = (const float*)d_in[1];
    const float* v  = (const float*)d_in[2];
    const float* Wq = (const float*)d_in[3];
    const float* bq = (const float*)d_in[4];
    const float* Wk = (const float*)d_in[5];
    const float* bk = (const float*)d_in[6];
    const float* Wv = (const float*)d_in[7];
    const float* bv = (const float*)d_in[8];
    const float* Wm = (const float*)d_in[9];
    const float* bm = (const float*)d_in[10];
    float* out = (float*)d_out;

    convert_kernel<<<(3 * XQ + 4 * WQ) / 256, 256>>>(q, k, v, Wq, Wk, Wv, Wm);
    qkv_proj_kernel<<<dim3(M_ROWS / 128, CDIM / 128, 3), 256>>>(bq, bk, bv);
    attn_mma_kernel<<<dim3(4, BTH), 256>>>();
    final_bf16_kernel<<<dim3(M_ROWS / 64, CDIM / 128), 256>>>(bm, q, out);
}

// round 12
// speedup vs baseline: 1.5539x; 1.5539x over previous
#include <cuda_runtime.h>
#include <cuda_bf16.h>
#include <cstdint>
#include <math.h>

// Problem constants: b=2, t=8, L=1024, c=256, H=8, D=32
#define M_ROWS 16384
#define CDIM   256
#define NHEAD  8
#define DHEAD  32
#define LSEQ   1024
#define BTH    128

// 1/sqrt(32) folded into Q at projection epilogue
#define QSCALE 0.17677669529663687f

// Scratch (device globals)
__device__ __nv_bfloat16 g_x16[12582912];  // q,k,v inputs in bf16
__device__ __nv_bfloat16 g_w16[262144];    // Wq,Wk,Wv,Wm in bf16
__device__ __nv_bfloat16 g_q16[4194304];   // [bth, l, d]  (pre-scaled)
__device__ __nv_bfloat16 g_k16[4194304];   // [bth, l, d]
__device__ __nv_bfloat16 g_v16[4194304];   // [bth, l, d]
__device__ __nv_bfloat16 g_att16[4194304]; // [bt, l, c]

// ---------------------------------------------------------------------------
__device__ __forceinline__ uint32_t smem_u32(const void* p) {
    uint32_t a;
    asm("{ .reg .u64 t; cvta.to.shared.u64 t, %1; cvt.u32.u64 %0, t; }" : "=r"(a) : "l"(p));
    return a;
}

#define LDSM_X4(r0, r1, r2, r3, addr) \
    asm volatile("ldmatrix.sync.aligned.m8n8.x4.shared.b16 {%0,%1,%2,%3}, [%4];" \
                 : "=r"(r0), "=r"(r1), "=r"(r2), "=r"(r3) : "r"(addr))
#define LDSM_X4T(r0, r1, r2, r3, addr) \
    asm volatile("ldmatrix.sync.aligned.m8n8.x4.trans.shared.b16 {%0,%1,%2,%3}, [%4];" \
                 : "=r"(r0), "=r"(r1), "=r"(r2), "=r"(r3) : "r"(addr))

#define MMA_BF16(c0, c1, c2, c3, a0, a1, a2, a3, b0, b1) \
    asm volatile("mma.sync.aligned.m16n8k16.row.col.f32.bf16.bf16.f32 " \
                 "{%0,%1,%2,%3}, {%4,%5,%6,%7}, {%8,%9}, {%0,%1,%2,%3};" \
                 : "+f"(c0), "+f"(c1), "+f"(c2), "+f"(c3) \
                 : "r"(a0), "r"(a1), "r"(a2), "r"(a3), "r"(b0), "r"(b1))

#define CVT_BF16X2(r, hi, lo) \
    asm("cvt.rn.bf16x2.f32 %0, %1, %2;" : "=r"(r) : "f"(hi), "f"(lo))

#define HFMA2_BF(d, a, b, cc) \
    asm("fma.rn.bf16x2 %0, %1, %2, %3;" : "=r"(d) : "r"(a), "r"(b), "r"(cc))

#define CP16(dst, src) \
    asm volatile("cp.async.cg.shared.global [%0], [%1], 16;" :: "r"(dst), "l"(src))
#define CP_COMMIT() asm volatile("cp.async.commit_group;")
#define CP_WAIT(n)  asm volatile("cp.async.wait_group %0;" :: "n"(n))

// bf16x2 constants for exp poly
#define ONES_BF16X2  0x3F803F80u
#define HALF_BF16X2  0x3F003F00u

// exp(x) for |x| <= 0.18: degree-2 Taylor in packed bf16x2.
// p = 1 + x*(1 + x*0.5). Truncation x^3/6 <= 9.2e-4 abs — below the bf16
// half-ulp P is rounded to before the PV MMA.
__device__ __forceinline__ uint32_t exp_bf16x2(uint32_t x) {
    uint32_t t;
    HFMA2_BF(t, x, HALF_BF16X2, ONES_BF16X2);
    HFMA2_BF(t, x, t, ONES_BF16X2);
    return t;
}

// ---------------------------------------------------------------------------
// Kernel 0: fp32 -> bf16 conversion of q,k,v and the 4 weight matrices.
// ---------------------------------------------------------------------------
#define XQ 1048576
#define WQ 16384
__global__ __launch_bounds__(256) void convert_kernel(
    const float* __restrict__ q, const float* __restrict__ k, const float* __restrict__ v,
    const float* __restrict__ Wq, const float* __restrict__ Wk,
    const float* __restrict__ Wv, const float* __restrict__ Wm)
{
    int idx = blockIdx.x * 256 + threadIdx.x;
    const float* src;
    uint2* dst;
    int local;
    if (idx < 3 * XQ) {
        int sel = idx / XQ;
        local = idx - sel * XQ;
        src = (sel == 0) ? q : (sel == 1) ? k : v;
        dst = (uint2*)g_x16 + idx;
    } else {
        int wi = idx - 3 * XQ;
        int sel = wi / WQ;
        local = wi - sel * WQ;
        src = (sel == 0) ? Wq : (sel == 1) ? Wk : (sel == 2) ? Wv : Wm;
        dst = (uint2*)g_w16 + wi;
    }
    float4 vv = ((const float4*)src)[local];
    uint32_t lo, hi;
    CVT_BF16X2(lo, vv.y, vv.x);
    CVT_BF16X2(hi, vv.w, vv.z);
    *dst = make_uint2(lo, hi);
}

// ---------------------------------------------------------------------------
// Kernel 1: merged q/k/v bf16 GEMM projection.
// 3-stage cp.async pipeline (prefetch distance 2), ONE barrier per chunk.
// ---------------------------------------------------------------------------
__global__ __launch_bounds__(256, 2) void qkv_proj_kernel(
    const float* __restrict__ bq, const float* __restrict__ bk,
    const float* __restrict__ bv)
{
    __shared__ __nv_bfloat16 Xs[3][128][40];
    __shared__ __nv_bfloat16 Ws[3][128][40];

    const int sel = blockIdx.z;
    const __nv_bfloat16* X = g_x16 + (size_t)sel * 4194304;
    const __nv_bfloat16* W = g_w16 + sel * 65536;
    const float* bias = (sel == 0) ? bq : (sel == 1) ? bk : bv;
    const float extra = (sel == 0) ? QSCALE : 1.0f;
    __nv_bfloat16* Out = (sel == 0) ? g_q16 : (sel == 1) ? g_k16 : g_v16;

    const int tid = threadIdx.x;
    const int w = tid >> 5, lane = tid & 31;
    const int wm = w >> 1, wn = w & 1;
    const int groupID = lane >> 2, tid4 = lane & 3;
    const int rowBase = blockIdx.x * 128;
    const int colBase = blockIdx.y * 128;

    const int lr0 = tid >> 2, lp0 = tid & 3;
    const int lr1 = lr0 + 64;

    float c[2][8][4];
#pragma unroll
    for (int mt = 0; mt < 2; ++mt)
#pragma unroll
        for (int nt = 0; nt < 8; ++nt)
#pragma unroll
            for (int i = 0; i < 4; ++i) c[mt][nt][i] = 0.f;

#pragma unroll
    for (int pc = 0; pc < 2; ++pc) {
        int ko = pc * 32;
        CP16(smem_u32(&Xs[pc][lr0][lp0 * 8]), X + (size_t)(rowBase + lr0) * CDIM + ko + lp0 * 8);
        CP16(smem_u32(&Xs[pc][lr1][lp0 * 8]), X + (size_t)(rowBase + lr1) * CDIM + ko + lp0 * 8);
        CP16(smem_u32(&Ws[pc][lr0][lp0 * 8]), W + (size_t)(colBase + lr0) * CDIM + ko + lp0 * 8);
        CP16(smem_u32(&Ws[pc][lr1][lp0 * 8]), W + (size_t)(colBase + lr1) * CDIM + ko + lp0 * 8);
        CP_COMMIT();
    }

#pragma unroll
    for (int kt = 0; kt < 8; ++kt) {
        const int cb = kt % 3;
        if (kt < 7) { CP_WAIT(1); } else { CP_WAIT(0); }
        __syncthreads();
        if (kt < 6) {
            const int nb = (kt + 2) % 3;
            int ko = (kt + 2) * 32;
            CP16(smem_u32(&Xs[nb][lr0][lp0 * 8]), X + (size_t)(rowBase + lr0) * CDIM + ko + lp0 * 8);
            CP16(smem_u32(&Xs[nb][lr1][lp0 * 8]), X + (size_t)(rowBase + lr1) * CDIM + ko + lp0 * 8);
            CP16(smem_u32(&Ws[nb][lr0][lp0 * 8]), W + (size_t)(colBase + lr0) * CDIM + ko + lp0 * 8);
            CP16(smem_u32(&Ws[nb][lr1][lp0 * 8]), W + (size_t)(colBase + lr1) * CDIM + ko + lp0 * 8);
            CP_COMMIT();
        }

        uint32_t a[2][2][4];
#pragma unroll
        for (int mt = 0; mt < 2; ++mt)
#pragma unroll
            for (int ks = 0; ks < 2; ++ks) {
                uint32_t addr = smem_u32(
                    &Xs[cb][wm * 32 + mt * 16 + (lane & 7) + ((lane & 8) ? 8 : 0)]
                       [ks * 16 + ((lane & 16) ? 8 : 0)]);
                LDSM_X4(a[mt][ks][0], a[mt][ks][1], a[mt][ks][2], a[mt][ks][3], addr);
            }
#pragma unroll
        for (int nt = 0; nt < 8; ++nt) {
            uint32_t b[4];
            uint32_t addr = smem_u32(&Ws[cb][wn * 64 + nt * 8 + (lane & 7)][(lane >> 3) * 8]);
            LDSM_X4(b[0], b[1], b[2], b[3], addr);
#pragma unroll
            for (int mt = 0; mt < 2; ++mt) {
                MMA_BF16(c[mt][nt][0], c[mt][nt][1], c[mt][nt][2], c[mt][nt][3],
                         a[mt][0][0], a[mt][0][1], a[mt][0][2], a[mt][0][3], b[0], b[1]);
                MMA_BF16(c[mt][nt][0], c[mt][nt][1], c[mt][nt][2], c[mt][nt][3],
                         a[mt][1][0], a[mt][1][1], a[mt][1][2], a[mt][1][3], b[2], b[3]);
            }
        }
    }

    float2 bj[8];
#pragma unroll
    for (int nt = 0; nt < 8; ++nt)
        bj[nt] = *(const float2*)(bias + colBase + wn * 64 + nt * 8 + tid4 * 2);
#pragma unroll
    for (int mt = 0; mt < 2; ++mt)
#pragma unroll
        for (int nt = 0; nt < 8; ++nt) {
            c[mt][nt][0] += bj[nt].x; c[mt][nt][1] += bj[nt].y;
            c[mt][nt][2] += bj[nt].x; c[mt][nt][3] += bj[nt].y;
        }

#pragma unroll
    for (int mt = 0; mt < 2; ++mt) {
        float ss[2][2];
        ss[0][0] = ss[0][1] = ss[1][0] = ss[1][1] = 0.f;
#pragma unroll
        for (int nt = 0; nt < 8; ++nt) {
            int hd = nt >> 2;
            ss[0][hd] += c[mt][nt][0] * c[mt][nt][0] + c[mt][nt][1] * c[mt][nt][1];
            ss[1][hd] += c[mt][nt][2] * c[mt][nt][2] + c[mt][nt][3] * c[mt][nt][3];
        }
        float scl[2][2];
#pragma unroll
        for (int rh = 0; rh < 2; ++rh)
#pragma unroll
            for (int hd = 0; hd < 2; ++hd) {
                float s = ss[rh][hd];
                s += __shfl_xor_sync(0xffffffffu, s, 1);
                s += __shfl_xor_sync(0xffffffffu, s, 2);
                scl[rh][hd] = extra / fmaxf(sqrtf(s), 1e-12f);
            }
#pragma unroll
        for (int rh = 0; rh < 2; ++rh) {
            int grow = rowBase + wm * 32 + mt * 16 + groupID + rh * 8;
            int bt = grow >> 10, l = grow & 1023;
#pragma unroll
            for (int nt = 0; nt < 8; ++nt) {
                int j = colBase + wn * 64 + nt * 8 + tid4 * 2;
                int h = j >> 5, dd = j & 31;
                float sc = scl[rh][nt >> 2];
                uint32_t pk;
                CVT_BF16X2(pk, c[mt][nt][rh * 2 + 1] * sc, c[mt][nt][rh * 2 + 0] * sc);
                *(uint32_t*)(Out + (((size_t)bt * NHEAD + h) * LSEQ + l) * DHEAD + dd) = pk;
            }
        }
    }
}

// ---------------------------------------------------------------------------
// Kernel 2: bf16 flash attention, m32 rows/warp, 128 threads, cp.async
// double-buffered, ONE barrier per tile. Row sums on tensor pipe via
// all-ones B-fragment; exp as packed-bf16x2 degree-2 poly (no online max).
// ---------------------------------------------------------------------------
__global__ __launch_bounds__(128, 4) void attn_mma_kernel()
{
    __shared__ __nv_bfloat16 sK[2][128][40];
    __shared__ __nv_bfloat16 sV[2][128][40];

    const int tid = threadIdx.x;
    const int w = tid >> 5, lane = tid & 31;
    const int groupID = lane >> 2, tid4 = lane & 3;
    const int bth = blockIdx.y, qt = blockIdx.x;

    const char* Qg = (const char*)(g_q16 + ((size_t)bth * LSEQ + qt * 128) * DHEAD);
    const char* Kg = (const char*)(g_k16 + (size_t)bth * LSEQ * DHEAD);
    const char* Vg = (const char*)(g_v16 + (size_t)bth * LSEQ * DHEAD);

    // Stage Q through sK[0]
#pragma unroll
    for (int i = 0; i < 4; ++i) {
        int f = tid + i * 128;
        int row = f >> 2, part = f & 3;
        *(float4*)(&sK[0][row][part * 8]) = *(const float4*)(Qg + row * 64 + part * 16);
    }
    __syncthreads();

    uint32_t qa[2][2][4];
#pragma unroll
    for (int mt = 0; mt < 2; ++mt)
#pragma unroll
        for (int kc = 0; kc < 2; ++kc) {
            int row = w * 32 + mt * 16 + (lane & 7) + ((lane & 8) ? 8 : 0);
            int col = kc * 16 + ((lane & 16) ? 8 : 0);
            uint32_t addr = smem_u32(&sK[0][row][col]);
            LDSM_X4(qa[mt][kc][0], qa[mt][kc][1], qa[mt][kc][2], qa[mt][kc][3], addr);
        }
    __syncthreads();

    // prologue: tile 0 -> buf 0
#pragma unroll
    for (int i = 0; i < 4; ++i) {
        int f = tid + i * 128;
        int row = f >> 2, part = f & 3;
        CP16(smem_u32(&sK[0][row][part * 8]), Kg + (size_t)row * 64 + part * 16);
        CP16(smem_u32(&sV[0][row][part * 8]), Vg + (size_t)row * 64 + part * 16);
    }
    CP_COMMIT();

    float o[2][4][4];
    float su[2][4];
#pragma unroll
    for (int mt = 0; mt < 2; ++mt) {
#pragma unroll
        for (int dn = 0; dn < 4; ++dn)
#pragma unroll
            for (int i = 0; i < 4; ++i) o[mt][dn][i] = 0.f;
#pragma unroll
        for (int i = 0; i < 4; ++i) su[mt][i] = 0.f;
    }

    for (int kt = 0; kt < 8; ++kt) {
        const int cb = kt & 1;
        CP_WAIT(0);
        __syncthreads();
        if (kt < 7) {
            const int nb = (kt + 1) & 1;
            const char* Kt = Kg + (size_t)(kt + 1) * 128 * 64;
            const char* Vt = Vg + (size_t)(kt + 1) * 128 * 64;
#pragma unroll
            for (int i = 0; i < 4; ++i) {
                int f = tid + i * 128;
                int row = f >> 2, part = f & 3;
                CP16(smem_u32(&sK[nb][row][part * 8]), Kt + (size_t)row * 64 + part * 16);
                CP16(smem_u32(&sV[nb][row][part * 8]), Vt + (size_t)row * 64 + part * 16);
            }
            CP_COMMIT();
        }

#pragma unroll
        for (int half = 0; half < 2; ++half) {
#pragma unroll
            for (int kc = 0; kc < 4; ++kc) {
                uint32_t pa[2][4];
#pragma unroll
                for (int sub = 0; sub < 2; ++sub) {
                    int nbk = half * 64 + (kc * 2 + sub) * 8;
                    uint32_t kb[4];
                    uint32_t addr = smem_u32(&sK[cb][nbk + (lane & 7)][(lane >> 3) * 8]);
                    LDSM_X4(kb[0], kb[1], kb[2], kb[3], addr);
#pragma unroll
                    for (int mt = 0; mt < 2; ++mt) {
                        float s0 = 0.f, s1 = 0.f, s2 = 0.f, s3 = 0.f;
                        MMA_BF16(s0, s1, s2, s3,
                                 qa[mt][0][0], qa[mt][0][1], qa[mt][0][2], qa[mt][0][3],
                                 kb[0], kb[1]);
                        MMA_BF16(s0, s1, s2, s3,
                                 qa[mt][1][0], qa[mt][1][1], qa[mt][1][2], qa[mt][1][3],
                                 kb[2], kb[3]);
                        uint32_t x01, x23;
                        CVT_BF16X2(x01, s1, s0);
                        CVT_BF16X2(x23, s3, s2);
                        pa[mt][sub * 2 + 0] = exp_bf16x2(x01);
                        pa[mt][sub * 2 + 1] = exp_bf16x2(x23);
                    }
                }
#pragma unroll
                for (int dp = 0; dp < 2; ++dp) {
                    uint32_t vb[4];
                    uint32_t addr = smem_u32(
                        &sV[cb][half * 64 + kc * 16 + (lane & 15)]
                           [dp * 16 + ((lane & 16) ? 8 : 0)]);
                    LDSM_X4T(vb[0], vb[1], vb[2], vb[3], addr);
#pragma unroll
                    for (int mt = 0; mt < 2; ++mt) {
                        MMA_BF16(o[mt][2 * dp][0], o[mt][2 * dp][1],
                                 o[mt][2 * dp][2], o[mt][2 * dp][3],
                                 pa[mt][0], pa[mt][1], pa[mt][2], pa[mt][3],
                                 vb[0], vb[1]);
                        MMA_BF16(o[mt][2 * dp + 1][0], o[mt][2 * dp + 1][1],
                                 o[mt][2 * dp + 1][2], o[mt][2 * dp + 1][3],
                                 pa[mt][0], pa[mt][1], pa[mt][2], pa[mt][3],
                                 vb[2], vb[3]);
                    }
                }
#pragma unroll
                for (int mt = 0; mt < 2; ++mt)
                    MMA_BF16(su[mt][0], su[mt][1], su[mt][2], su[mt][3],
                             pa[mt][0], pa[mt][1], pa[mt][2], pa[mt][3],
                             ONES_BF16X2, ONES_BF16X2);
            }
        }
    }

    const int bt = bth >> 3, h = bth & 7;
#pragma unroll
    for (int mt = 0; mt < 2; ++mt) {
        const float inv0 = 1.f / su[mt][0];
        const float inv1 = 1.f / su[mt][2];
        const int l0 = qt * 128 + w * 32 + mt * 16 + groupID;
#pragma unroll
        for (int dn = 0; dn < 4; ++dn) {
            int col = h * DHEAD + dn * 8 + tid4 * 2;
            uint32_t pk0, pk1;
            CVT_BF16X2(pk0, o[mt][dn][1] * inv0, o[mt][dn][0] * inv0);
            CVT_BF16X2(pk1, o[mt][dn][3] * inv1, o[mt][dn][2] * inv1);
            *(uint32_t*)(g_att16 + ((size_t)bt * LSEQ + l0) * CDIM + col) = pk0;
            *(uint32_t*)(g_att16 + ((size_t)bt * LSEQ + l0 + 8) * CDIM + col) = pk1;
        }
    }
}

// ---------------------------------------------------------------------------
// Kernel 3: Out = g_att16 @ Wm^T + bm + shortcut (fp32 out).
// 128x128 tiles, 3-stage cp.async pipeline, ONE barrier per chunk.
// ---------------------------------------------------------------------------
__global__ __launch_bounds__(256, 2) void final_bf16_kernel(
    const float* __restrict__ bias, const float* __restrict__ shortcut,
    float* __restrict__ Out)
{
    __shared__ __nv_bfloat16 Xs[3][128][40];
    __shared__ __nv_bfloat16 Ws[3][128][40];

    const __nv_bfloat16* X = g_att16;
    const __nv_bfloat16* W = g_w16 + 3 * 65536;

    const int tid = threadIdx.x;
    const int w = tid >> 5, lane = tid & 31;
    const int wm = w >> 1, wn = w & 1;
    const int groupID = lane >> 2, tid4 = lane & 3;
    const int rowBase = blockIdx.x * 128;
    const int colBase = blockIdx.y * 128;

    const int lr0 = tid >> 2, lp0 = tid & 3;
    const int lr1 = lr0 + 64;

    float c[2][8][4];
#pragma unroll
    for (int mt = 0; mt < 2; ++mt)
#pragma unroll
        for (int nt = 0; nt < 8; ++nt)
#pragma unroll
            for (int i = 0; i < 4; ++i) c[mt][nt][i] = 0.f;

#pragma unroll
    for (int pc = 0; pc < 2; ++pc) {
        int ko = pc * 32;
        CP16(smem_u32(&Xs[pc][lr0][lp0 * 8]), X + (size_t)(rowBase + lr0) * CDIM + ko + lp0 * 8);
        CP16(smem_u32(&Xs[pc][lr1][lp0 * 8]), X + (size_t)(rowBase + lr1) * CDIM + ko + lp0 * 8);
        CP16(smem_u32(&Ws[pc][lr0][lp0 * 8]), W + (size_t)(colBase + lr0) * CDIM + ko + lp0 * 8);
        CP16(smem_u32(&Ws[pc][lr1][lp0 * 8]), W + (size_t)(colBase + lr1) * CDIM + ko + lp0 * 8);
        CP_COMMIT();
    }

#pragma unroll
    for (int kt = 0; kt < 8; ++kt) {
        const int cb = kt % 3;
        if (kt < 7) { CP_WAIT(1); } else { CP_WAIT(0); }
        __syncthreads();
        if (kt < 6) {
            const int nb = (kt + 2) % 3;
            int ko = (kt + 2) * 32;
            CP16(smem_u32(&Xs[nb][lr0][lp0 * 8]), X + (size_t)(rowBase + lr0) * CDIM + ko + lp0 * 8);
            CP16(smem_u32(&Xs[nb][lr1][lp0 * 8]), X + (size_t)(rowBase + lr1) * CDIM + ko + lp0 * 8);
            CP16(smem_u32(&Ws[nb][lr0][lp0 * 8]), W + (size_t)(colBase + lr0) * CDIM + ko + lp0 * 8);
            CP16(smem_u32(&Ws[nb][lr1][lp0 * 8]), W + (size_t)(colBase + lr1) * CDIM + ko + lp0 * 8);
            CP_COMMIT();
        }

        uint32_t a[2][2][4];
#pragma unroll
        for (int mt = 0; mt < 2; ++mt)
#pragma unroll
            for (int ks = 0; ks < 2; ++ks) {
                uint32_t addr = smem_u32(
                    &Xs[cb][wm * 32 + mt * 16 + (lane & 7) + ((lane & 8) ? 8 : 0)]
                       [ks * 16 + ((lane & 16) ? 8 : 0)]);
                LDSM_X4(a[mt][ks][0], a[mt][ks][1], a[mt][ks][2], a[mt][ks][3], addr);
            }
#pragma unroll
        for (int nt = 0; nt < 8; ++nt) {
            uint32_t b[4];
            uint32_t addr = smem_u32(&Ws[cb][wn * 64 + nt * 8 + (lane & 7)][(lane >> 3) * 8]);
            LDSM_X4(b[0], b[1], b[2], b[3], addr);
#pragma unroll
            for (int mt = 0; mt < 2; ++mt) {
                MMA_BF16(c[mt][nt][0], c[mt][nt][1], c[mt][nt][2], c[mt][nt][3],
                         a[mt][0][0], a[mt][0][1], a[mt][0][2], a[mt][0][3], b[0], b[1]);
                MMA_BF16(c[mt][nt][0], c[mt][nt][1], c[mt][nt][2], c[mt][nt][3],
                         a[mt][1][0], a[mt][1][1], a[mt][1][2], a[mt][1][3], b[2], b[3]);
            }
        }
    }

    float2 bj[8];
#pragma unroll
    for (int nt = 0; nt < 8; ++nt)
        bj[nt] = *(const float2*)(bias + colBase + wn * 64 + nt * 8 + tid4 * 2);

#pragma unroll
    for (int mt = 0; mt < 2; ++mt)
#pragma unroll
        for (int rh = 0; rh < 2; ++rh) {
            int grow = rowBase + wm * 32 + mt * 16 + groupID + rh * 8;
#pragma unroll
            for (int nt = 0; nt < 8; ++nt) {
                int j = colBase + wn * 64 + nt * 8 + tid4 * 2;
                size_t addr = (size_t)grow * CDIM + j;
                float2 sc = *(const float2*)(shortcut + addr);
                float2 ov;
                ov.x = c[mt][nt][rh * 2 + 0] + bj[nt].x + sc.x;
                ov.y = c[mt][nt][rh * 2 + 1] + bj[nt].y + sc.y;
                *(float2*)(Out + addr) = ov;
            }
        }
}

// ---------------------------------------------------------------------------
extern "C" void kernel_launch(void* const* d_in, const int* in_sizes, int n_in,
                              void* d_out, int out_size)
{
    const float* q  = (const float*)d_in[0];
    const float* k  = (const float*)d_in[1];
    const float* v  = (const float*)d_in[2];
    const float* Wq = (const float*)d_in[3];
    const float* bq = (const float*)d_in[4];
    const float* Wk = (const float*)d_in[5];
    const float* bk = (const float*)d_in[6];
    const float* Wv = (const float*)d_in[7];
    const float* bv = (const float*)d_in[8];
    const float* Wm = (const float*)d_in[9];
    const float* bm = (const float*)d_in[10];
    float* out = (float*)d_out;

    convert_kernel<<<(3 * XQ + 4 * WQ) / 256, 256>>>(q, k, v, Wq, Wk, Wv, Wm);
    qkv_proj_kernel<<<dim3(M_ROWS / 128, CDIM / 128, 3), 256>>>(bq, bk, bv);
    attn_mma_kernel<<<dim3(8, BTH), 128>>>();
    final_bf16_kernel<<<dim3(M_ROWS / 128, CDIM / 128), 256>>>(bm, q, out);
}

// round 13
// speedup vs baseline: 1.5981x; 1.0284x over previous
#include <cuda_runtime.h>
#include <cuda_fp16.h>
#include <cstdint>
#include <math.h>

// Problem constants: b=2, t=8, L=1024, c=256, H=8, D=32
#define M_ROWS 16384
#define CDIM   256
#define NHEAD  8
#define DHEAD  32
#define LSEQ   1024
#define BTH    128

// 1/sqrt(32) folded into Q at projection epilogue
#define QSCALE 0.17677669529663687f

// Scratch (device globals) — all 16-bit tensors are fp16 now
__device__ __half g_x16[12582912];  // q,k,v inputs
__device__ __half g_w16[262144];    // Wq,Wk,Wv,Wm
__device__ __half g_q16[4194304];   // [bth, l, d]  (pre-scaled)
__device__ __half g_k16[4194304];   // [bth, l, d]
__device__ __half g_v16[4194304];   // [bth, l, d]
__device__ __half g_att16[4194304]; // [bt, l, c]

// ---------------------------------------------------------------------------
__device__ __forceinline__ uint32_t smem_u32(const void* p) {
    uint32_t a;
    asm("{ .reg .u64 t; cvta.to.shared.u64 t, %1; cvt.u32.u64 %0, t; }" : "=r"(a) : "l"(p));
    return a;
}

#define LDSM_X4(r0, r1, r2, r3, addr) \
    asm volatile("ldmatrix.sync.aligned.m8n8.x4.shared.b16 {%0,%1,%2,%3}, [%4];" \
                 : "=r"(r0), "=r"(r1), "=r"(r2), "=r"(r3) : "r"(addr))
#define LDSM_X4T(r0, r1, r2, r3, addr) \
    asm volatile("ldmatrix.sync.aligned.m8n8.x4.trans.shared.b16 {%0,%1,%2,%3}, [%4];" \
                 : "=r"(r0), "=r"(r1), "=r"(r2), "=r"(r3) : "r"(addr))

// f16 operands, f32 accumulator (GEMMs, PV, row sums)
#define MMA_F16F32(c0, c1, c2, c3, a0, a1, a2, a3, b0, b1) \
    asm volatile("mma.sync.aligned.m16n8k16.row.col.f32.f16.f16.f32 " \
                 "{%0,%1,%2,%3}, {%4,%5,%6,%7}, {%8,%9}, {%0,%1,%2,%3};" \
                 : "+f"(c0), "+f"(c1), "+f"(c2), "+f"(c3) \
                 : "r"(a0), "r"(a1), "r"(a2), "r"(a3), "r"(b0), "r"(b1))

// f16 operands, f16 accumulator (QK^T): D/C are 2 packed f16x2 regs
#define MMA_F16ACC(d0, d1, a0, a1, a2, a3, b0, b1) \
    asm volatile("mma.sync.aligned.m16n8k16.row.col.f16.f16.f16.f16 " \
                 "{%0,%1}, {%2,%3,%4,%5}, {%6,%7}, {%0,%1};" \
                 : "+r"(d0), "+r"(d1) \
                 : "r"(a0), "r"(a1), "r"(a2), "r"(a3), "r"(b0), "r"(b1))

#define CVT_F16X2(r, hi, lo) \
    asm("cvt.rn.f16x2.f32 %0, %1, %2;" : "=r"(r) : "f"(hi), "f"(lo))

#define HFMA2_F16(d, a, b, cc) \
    asm("fma.rn.f16x2 %0, %1, %2, %3;" : "=r"(d) : "r"(a), "r"(b), "r"(cc))

#define CP16(dst, src) \
    asm volatile("cp.async.cg.shared.global [%0], [%1], 16;" :: "r"(dst), "l"(src))
#define CP_COMMIT() asm volatile("cp.async.commit_group;")
#define CP_WAIT(n)  asm volatile("cp.async.wait_group %0;" :: "n"(n))

// f16x2 constants
#define ONES_F16X2  0x3C003C00u   // (1.0, 1.0)
#define HALF_F16X2  0x38003800u   // (0.5, 0.5)

// exp(x) for |x| <= 0.18: degree-2 Taylor in packed f16x2 (in-place on MMA output)
__device__ __forceinline__ uint32_t exp_f16x2(uint32_t x) {
    uint32_t t;
    HFMA2_F16(t, x, HALF_F16X2, ONES_F16X2);
    HFMA2_F16(t, x, t, ONES_F16X2);
    return t;
}

// ---------------------------------------------------------------------------
// Kernel 0: fp32 -> fp16 conversion of q,k,v and the 4 weight matrices.
// ---------------------------------------------------------------------------
#define XQ 1048576
#define WQ 16384
__global__ __launch_bounds__(256) void convert_kernel(
    const float* __restrict__ q, const float* __restrict__ k, const float* __restrict__ v,
    const float* __restrict__ Wq, const float* __restrict__ Wk,
    const float* __restrict__ Wv, const float* __restrict__ Wm)
{
    int idx = blockIdx.x * 256 + threadIdx.x;
    const float* src;
    uint2* dst;
    int local;
    if (idx < 3 * XQ) {
        int sel = idx / XQ;
        local = idx - sel * XQ;
        src = (sel == 0) ? q : (sel == 1) ? k : v;
        dst = (uint2*)g_x16 + idx;
    } else {
        int wi = idx - 3 * XQ;
        int sel = wi / WQ;
        local = wi - sel * WQ;
        src = (sel == 0) ? Wq : (sel == 1) ? Wk : (sel == 2) ? Wv : Wm;
        dst = (uint2*)g_w16 + wi;
    }
    float4 vv = ((const float4*)src)[local];
    uint32_t lo, hi;
    CVT_F16X2(lo, vv.y, vv.x);
    CVT_F16X2(hi, vv.w, vv.z);
    *dst = make_uint2(lo, hi);
}

// ---------------------------------------------------------------------------
// Kernel 1: merged q/k/v fp16 GEMM projection.
// 3-stage cp.async pipeline (prefetch distance 2), ONE barrier per chunk.
// ---------------------------------------------------------------------------
__global__ __launch_bounds__(256, 2) void qkv_proj_kernel(
    const float* __restrict__ bq, const float* __restrict__ bk,
    const float* __restrict__ bv)
{
    __shared__ __half Xs[3][128][40];
    __shared__ __half Ws[3][128][40];

    const int sel = blockIdx.z;
    const __half* X = g_x16 + (size_t)sel * 4194304;
    const __half* W = g_w16 + sel * 65536;
    const float* bias = (sel == 0) ? bq : (sel == 1) ? bk : bv;
    const float extra = (sel == 0) ? QSCALE : 1.0f;
    __half* Out = (sel == 0) ? g_q16 : (sel == 1) ? g_k16 : g_v16;

    const int tid = threadIdx.x;
    const int w = tid >> 5, lane = tid & 31;
    const int wm = w >> 1, wn = w & 1;
    const int groupID = lane >> 2, tid4 = lane & 3;
    const int rowBase = blockIdx.x * 128;
    const int colBase = blockIdx.y * 128;

    const int lr0 = tid >> 2, lp0 = tid & 3;
    const int lr1 = lr0 + 64;

    float c[2][8][4];
#pragma unroll
    for (int mt = 0; mt < 2; ++mt)
#pragma unroll
        for (int nt = 0; nt < 8; ++nt)
#pragma unroll
            for (int i = 0; i < 4; ++i) c[mt][nt][i] = 0.f;

#pragma unroll
    for (int pc = 0; pc < 2; ++pc) {
        int ko = pc * 32;
        CP16(smem_u32(&Xs[pc][lr0][lp0 * 8]), X + (size_t)(rowBase + lr0) * CDIM + ko + lp0 * 8);
        CP16(smem_u32(&Xs[pc][lr1][lp0 * 8]), X + (size_t)(rowBase + lr1) * CDIM + ko + lp0 * 8);
        CP16(smem_u32(&Ws[pc][lr0][lp0 * 8]), W + (size_t)(colBase + lr0) * CDIM + ko + lp0 * 8);
        CP16(smem_u32(&Ws[pc][lr1][lp0 * 8]), W + (size_t)(colBase + lr1) * CDIM + ko + lp0 * 8);
        CP_COMMIT();
    }

#pragma unroll
    for (int kt = 0; kt < 8; ++kt) {
        const int cb = kt % 3;
        if (kt < 7) { CP_WAIT(1); } else { CP_WAIT(0); }
        __syncthreads();
        if (kt < 6) {
            const int nb = (kt + 2) % 3;
            int ko = (kt + 2) * 32;
            CP16(smem_u32(&Xs[nb][lr0][lp0 * 8]), X + (size_t)(rowBase + lr0) * CDIM + ko + lp0 * 8);
            CP16(smem_u32(&Xs[nb][lr1][lp0 * 8]), X + (size_t)(rowBase + lr1) * CDIM + ko + lp0 * 8);
            CP16(smem_u32(&Ws[nb][lr0][lp0 * 8]), W + (size_t)(colBase + lr0) * CDIM + ko + lp0 * 8);
            CP16(smem_u32(&Ws[nb][lr1][lp0 * 8]), W + (size_t)(colBase + lr1) * CDIM + ko + lp0 * 8);
            CP_COMMIT();
        }

        uint32_t a[2][2][4];
#pragma unroll
        for (int mt = 0; mt < 2; ++mt)
#pragma unroll
            for (int ks = 0; ks < 2; ++ks) {
                uint32_t addr = smem_u32(
                    &Xs[cb][wm * 32 + mt * 16 + (lane & 7) + ((lane & 8) ? 8 : 0)]
                       [ks * 16 + ((lane & 16) ? 8 : 0)]);
                LDSM_X4(a[mt][ks][0], a[mt][ks][1], a[mt][ks][2], a[mt][ks][3], addr);
            }
#pragma unroll
        for (int nt = 0; nt < 8; ++nt) {
            uint32_t b[4];
            uint32_t addr = smem_u32(&Ws[cb][wn * 64 + nt * 8 + (lane & 7)][(lane >> 3) * 8]);
            LDSM_X4(b[0], b[1], b[2], b[3], addr);
#pragma unroll
            for (int mt = 0; mt < 2; ++mt) {
                MMA_F16F32(c[mt][nt][0], c[mt][nt][1], c[mt][nt][2], c[mt][nt][3],
                           a[mt][0][0], a[mt][0][1], a[mt][0][2], a[mt][0][3], b[0], b[1]);
                MMA_F16F32(c[mt][nt][0], c[mt][nt][1], c[mt][nt][2], c[mt][nt][3],
                           a[mt][1][0], a[mt][1][1], a[mt][1][2], a[mt][1][3], b[2], b[3]);
            }
        }
    }

    float2 bj[8];
#pragma unroll
    for (int nt = 0; nt < 8; ++nt)
        bj[nt] = *(const float2*)(bias + colBase + wn * 64 + nt * 8 + tid4 * 2);
#pragma unroll
    for (int mt = 0; mt < 2; ++mt)
#pragma unroll
        for (int nt = 0; nt < 8; ++nt) {
            c[mt][nt][0] += bj[nt].x; c[mt][nt][1] += bj[nt].y;
            c[mt][nt][2] += bj[nt].x; c[mt][nt][3] += bj[nt].y;
        }

#pragma unroll
    for (int mt = 0; mt < 2; ++mt) {
        float ss[2][2];
        ss[0][0] = ss[0][1] = ss[1][0] = ss[1][1] = 0.f;
#pragma unroll
        for (int nt = 0; nt < 8; ++nt) {
            int hd = nt >> 2;
            ss[0][hd] += c[mt][nt][0] * c[mt][nt][0] + c[mt][nt][1] * c[mt][nt][1];
            ss[1][hd] += c[mt][nt][2] * c[mt][nt][2] + c[mt][nt][3] * c[mt][nt][3];
        }
        float scl[2][2];
#pragma unroll
        for (int rh = 0; rh < 2; ++rh)
#pragma unroll
            for (int hd = 0; hd < 2; ++hd) {
                float s = ss[rh][hd];
                s += __shfl_xor_sync(0xffffffffu, s, 1);
                s += __shfl_xor_sync(0xffffffffu, s, 2);
                scl[rh][hd] = extra / fmaxf(sqrtf(s), 1e-12f);
            }
#pragma unroll
        for (int rh = 0; rh < 2; ++rh) {
            int grow = rowBase + wm * 32 + mt * 16 + groupID + rh * 8;
            int bt = grow >> 10, l = grow & 1023;
#pragma unroll
            for (int nt = 0; nt < 8; ++nt) {
                int j = colBase + wn * 64 + nt * 8 + tid4 * 2;
                int h = j >> 5, dd = j & 31;
                float sc = scl[rh][nt >> 2];
                uint32_t pk;
                CVT_F16X2(pk, c[mt][nt][rh * 2 + 1] * sc, c[mt][nt][rh * 2 + 0] * sc);
                *(uint32_t*)(Out + (((size_t)bt * NHEAD + h) * LSEQ + l) * DHEAD + dd) = pk;
            }
        }
    }
}

// ---------------------------------------------------------------------------
// Kernel 2: fp16 flash attention, m32 rows/warp, 128 threads, cp.async
// double-buffered, ONE barrier per tile. QK^T with f16 accumulator -> S
// already packed f16x2 in A-fragment layout; exp in-place (no CVTs).
// Row sums on tensor pipe (f32 accum); no online max (|s| <= 0.177).
// ---------------------------------------------------------------------------
__global__ __launch_bounds__(128, 4) void attn_mma_kernel()
{
    __shared__ __half sK[2][128][40];
    __shared__ __half sV[2][128][40];

    const int tid = threadIdx.x;
    const int w = tid >> 5, lane = tid & 31;
    const int groupID = lane >> 2, tid4 = lane & 3;
    const int bth = blockIdx.y, qt = blockIdx.x;

    const char* Qg = (const char*)(g_q16 + ((size_t)bth * LSEQ + qt * 128) * DHEAD);
    const char* Kg = (const char*)(g_k16 + (size_t)bth * LSEQ * DHEAD);
    const char* Vg = (const char*)(g_v16 + (size_t)bth * LSEQ * DHEAD);

    // Stage Q through sK[0]
#pragma unroll
    for (int i = 0; i < 4; ++i) {
        int f = tid + i * 128;
        int row = f >> 2, part = f & 3;
        *(float4*)(&sK[0][row][part * 8]) = *(const float4*)(Qg + row * 64 + part * 16);
    }
    __syncthreads();

    uint32_t qa[2][2][4];
#pragma unroll
    for (int mt = 0; mt < 2; ++mt)
#pragma unroll
        for (int kc = 0; kc < 2; ++kc) {
            int row = w * 32 + mt * 16 + (lane & 7) + ((lane & 8) ? 8 : 0);
            int col = kc * 16 + ((lane & 16) ? 8 : 0);
            uint32_t addr = smem_u32(&sK[0][row][col]);
            LDSM_X4(qa[mt][kc][0], qa[mt][kc][1], qa[mt][kc][2], qa[mt][kc][3], addr);
        }
    __syncthreads();

    // prologue: tile 0 -> buf 0
#pragma unroll
    for (int i = 0; i < 4; ++i) {
        int f = tid + i * 128;
        int row = f >> 2, part = f & 3;
        CP16(smem_u32(&sK[0][row][part * 8]), Kg + (size_t)row * 64 + part * 16);
        CP16(smem_u32(&sV[0][row][part * 8]), Vg + (size_t)row * 64 + part * 16);
    }
    CP_COMMIT();

    float o[2][4][4];
    float su[2][4];
#pragma unroll
    for (int mt = 0; mt < 2; ++mt) {
#pragma unroll
        for (int dn = 0; dn < 4; ++dn)
#pragma unroll
            for (int i = 0; i < 4; ++i) o[mt][dn][i] = 0.f;
#pragma unroll
        for (int i = 0; i < 4; ++i) su[mt][i] = 0.f;
    }

    for (int kt = 0; kt < 8; ++kt) {
        const int cb = kt & 1;
        CP_WAIT(0);
        __syncthreads();
        if (kt < 7) {
            const int nb = (kt + 1) & 1;
            const char* Kt = Kg + (size_t)(kt + 1) * 128 * 64;
            const char* Vt = Vg + (size_t)(kt + 1) * 128 * 64;
#pragma unroll
            for (int i = 0; i < 4; ++i) {
                int f = tid + i * 128;
                int row = f >> 2, part = f & 3;
                CP16(smem_u32(&sK[nb][row][part * 8]), Kt + (size_t)row * 64 + part * 16);
                CP16(smem_u32(&sV[nb][row][part * 8]), Vt + (size_t)row * 64 + part * 16);
            }
            CP_COMMIT();
        }

#pragma unroll
        for (int half = 0; half < 2; ++half) {
#pragma unroll
            for (int kc = 0; kc < 4; ++kc) {
                uint32_t pa[2][4];
#pragma unroll
                for (int sub = 0; sub < 2; ++sub) {
                    int nbk = half * 64 + (kc * 2 + sub) * 8;
                    uint32_t kb[4];
                    uint32_t addr = smem_u32(&sK[cb][nbk + (lane & 7)][(lane >> 3) * 8]);
                    LDSM_X4(kb[0], kb[1], kb[2], kb[3], addr);
#pragma unroll
                    for (int mt = 0; mt < 2; ++mt) {
                        uint32_t d0 = 0u, d1 = 0u;   // f16x2 accumulators
                        MMA_F16ACC(d0, d1,
                                   qa[mt][0][0], qa[mt][0][1], qa[mt][0][2], qa[mt][0][3],
                                   kb[0], kb[1]);
                        MMA_F16ACC(d0, d1,
                                   qa[mt][1][0], qa[mt][1][1], qa[mt][1][2], qa[mt][1][3],
                                   kb[2], kb[3]);
                        pa[mt][sub * 2 + 0] = exp_f16x2(d0);   // rows g
                        pa[mt][sub * 2 + 1] = exp_f16x2(d1);   // rows g+8
                    }
                }
#pragma unroll
                for (int dp = 0; dp < 2; ++dp) {
                    uint32_t vb[4];
                    uint32_t addr = smem_u32(
                        &sV[cb][half * 64 + kc * 16 + (lane & 15)]
                           [dp * 16 + ((lane & 16) ? 8 : 0)]);
                    LDSM_X4T(vb[0], vb[1], vb[2], vb[3], addr);
#pragma unroll
                    for (int mt = 0; mt < 2; ++mt) {
                        MMA_F16F32(o[mt][2 * dp][0], o[mt][2 * dp][1],
                                   o[mt][2 * dp][2], o[mt][2 * dp][3],
                                   pa[mt][0], pa[mt][1], pa[mt][2], pa[mt][3],
                                   vb[0], vb[1]);
                        MMA_F16F32(o[mt][2 * dp + 1][0], o[mt][2 * dp + 1][1],
                                   o[mt][2 * dp + 1][2], o[mt][2 * dp + 1][3],
                                   pa[mt][0], pa[mt][1], pa[mt][2], pa[mt][3],
                                   vb[2], vb[3]);
                    }
                }
#pragma unroll
                for (int mt = 0; mt < 2; ++mt)
                    MMA_F16F32(su[mt][0], su[mt][1], su[mt][2], su[mt][3],
                               pa[mt][0], pa[mt][1], pa[mt][2], pa[mt][3],
                               ONES_F16X2, ONES_F16X2);
            }
        }
    }

    const int bt = bth >> 3, h = bth & 7;
#pragma unroll
    for (int mt = 0; mt < 2; ++mt) {
        const float inv0 = 1.f / su[mt][0];
        const float inv1 = 1.f / su[mt][2];
        const int l0 = qt * 128 + w * 32 + mt * 16 + groupID;
#pragma unroll
        for (int dn = 0; dn < 4; ++dn) {
            int col = h * DHEAD + dn * 8 + tid4 * 2;
            uint32_t pk0, pk1;
            CVT_F16X2(pk0, o[mt][dn][1] * inv0, o[mt][dn][0] * inv0);
            CVT_F16X2(pk1, o[mt][dn][3] * inv1, o[mt][dn][2] * inv1);
            *(uint32_t*)(g_att16 + ((size_t)bt * LSEQ + l0) * CDIM + col) = pk0;
            *(uint32_t*)(g_att16 + ((size_t)bt * LSEQ + l0 + 8) * CDIM + col) = pk1;
        }
    }
}

// ---------------------------------------------------------------------------
// Kernel 3: Out = g_att16 @ Wm^T + bm + shortcut (fp32 out).
// 128x128 tiles, 3-stage cp.async pipeline, ONE barrier per chunk.
// ---------------------------------------------------------------------------
__global__ __launch_bounds__(256, 2) void final_f16_kernel(
    const float* __restrict__ bias, const float* __restrict__ shortcut,
    float* __restrict__ Out)
{
    __shared__ __half Xs[3][128][40];
    __shared__ __half Ws[3][128][40];

    const __half* X = g_att16;
    const __half* W = g_w16 + 3 * 65536;

    const int tid = threadIdx.x;
    const int w = tid >> 5, lane = tid & 31;
    const int wm = w >> 1, wn = w & 1;
    const int groupID = lane >> 2, tid4 = lane & 3;
    const int rowBase = blockIdx.x * 128;
    const int colBase = blockIdx.y * 128;

    const int lr0 = tid >> 2, lp0 = tid & 3;
    const int lr1 = lr0 + 64;

    float c[2][8][4];
#pragma unroll
    for (int mt = 0; mt < 2; ++mt)
#pragma unroll
        for (int nt = 0; nt < 8; ++nt)
#pragma unroll
            for (int i = 0; i < 4; ++i) c[mt][nt][i] = 0.f;

#pragma unroll
    for (int pc = 0; pc < 2; ++pc) {
        int ko = pc * 32;
        CP16(smem_u32(&Xs[pc][lr0][lp0 * 8]), X + (size_t)(rowBase + lr0) * CDIM + ko + lp0 * 8);
        CP16(smem_u32(&Xs[pc][lr1][lp0 * 8]), X + (size_t)(rowBase + lr1) * CDIM + ko + lp0 * 8);
        CP16(smem_u32(&Ws[pc][lr0][lp0 * 8]), W + (size_t)(colBase + lr0) * CDIM + ko + lp0 * 8);
        CP16(smem_u32(&Ws[pc][lr1][lp0 * 8]), W + (size_t)(colBase + lr1) * CDIM + ko + lp0 * 8);
        CP_COMMIT();
    }

#pragma unroll
    for (int kt = 0; kt < 8; ++kt) {
        const int cb = kt % 3;
        if (kt < 7) { CP_WAIT(1); } else { CP_WAIT(0); }
        __syncthreads();
        if (kt < 6) {
            const int nb = (kt + 2) % 3;
            int ko = (kt + 2) * 32;
            CP16(smem_u32(&Xs[nb][lr0][lp0 * 8]), X + (size_t)(rowBase + lr0) * CDIM + ko + lp0 * 8);
            CP16(smem_u32(&Xs[nb][lr1][lp0 * 8]), X + (size_t)(rowBase + lr1) * CDIM + ko + lp0 * 8);
            CP16(smem_u32(&Ws[nb][lr0][lp0 * 8]), W + (size_t)(colBase + lr0) * CDIM + ko + lp0 * 8);
            CP16(smem_u32(&Ws[nb][lr1][lp0 * 8]), W + (size_t)(colBase + lr1) * CDIM + ko + lp0 * 8);
            CP_COMMIT();
        }

        uint32_t a[2][2][4];
#pragma unroll
        for (int mt = 0; mt < 2; ++mt)
#pragma unroll
            for (int ks = 0; ks < 2; ++ks) {
                uint32_t addr = smem_u32(
                    &Xs[cb][wm * 32 + mt * 16 + (lane & 7) + ((lane & 8) ? 8 : 0)]
                       [ks * 16 + ((lane & 16) ? 8 : 0)]);
                LDSM_X4(a[mt][ks][0], a[mt][ks][1], a[mt][ks][2], a[mt][ks][3], addr);
            }
#pragma unroll
        for (int nt = 0; nt < 8; ++nt) {
            uint32_t b[4];
            uint32_t addr = smem_u32(&Ws[cb][wn * 64 + nt * 8 + (lane & 7)][(lane >> 3) * 8]);
            LDSM_X4(b[0], b[1], b[2], b[3], addr);
#pragma unroll
            for (int mt = 0; mt < 2; ++mt) {
                MMA_F16F32(c[mt][nt][0], c[mt][nt][1], c[mt][nt][2], c[mt][nt][3],
                           a[mt][0][0], a[mt][0][1], a[mt][0][2], a[mt][0][3], b[0], b[1]);
                MMA_F16F32(c[mt][nt][0], c[mt][nt][1], c[mt][nt][2], c[mt][nt][3],
                           a[mt][1][0], a[mt][1][1], a[mt][1][2], a[mt][1][3], b[2], b[3]);
            }
        }
    }

    float2 bj[8];
#pragma unroll
    for (int nt = 0; nt < 8; ++nt)
        bj[nt] = *(const float2*)(bias + colBase + wn * 64 + nt * 8 + tid4 * 2);

#pragma unroll
    for (int mt = 0; mt < 2; ++mt)
#pragma unroll
        for (int rh = 0; rh < 2; ++rh) {
            int grow = rowBase + wm * 32 + mt * 16 + groupID + rh * 8;
#pragma unroll
            for (int nt = 0; nt < 8; ++nt) {
                int j = colBase + wn * 64 + nt * 8 + tid4 * 2;
                size_t addr = (size_t)grow * CDIM + j;
                float2 sc = *(const float2*)(shortcut + addr);
                float2 ov;
                ov.x = c[mt][nt][rh * 2 + 0] + bj[nt].x + sc.x;
                ov.y = c[mt][nt][rh * 2 + 1] + bj[nt].y + sc.y;
                *(float2*)(Out + addr) = ov;
            }
        }
}

// ---------------------------------------------------------------------------
extern "C" void kernel_launch(void* const* d_in, const int* in_sizes, int n_in,
                              void* d_out, int out_size)
{
    const float* q  = (const float*)d_in[0];
    const float* k  = (const float*)d_in[1];
    const float* v  = (const float*)d_in[2];
    const float* Wq = (const float*)d_in[3];
    const float* bq = (const float*)d_in[4];
    const float* Wk = (const float*)d_in[5];
    const float* bk = (const float*)d_in[6];
    const float* Wv = (const float*)d_in[7];
    const float* bv = (const float*)d_in[8];
    const float* Wm = (const float*)d_in[9];
    const float* bm = (const float*)d_in[10];
    float* out = (float*)d_out;

    convert_kernel<<<(3 * XQ + 4 * WQ) / 256, 256>>>(q, k, v, Wq, Wk, Wv, Wm);
    qkv_proj_kernel<<<dim3(M_ROWS / 128, CDIM / 128, 3), 256>>>(bq, bk, bv);
    attn_mma_kernel<<<dim3(8, BTH), 128>>>();
    final_f16_kernel<<<dim3(M_ROWS / 128, CDIM / 128), 256>>>(bm, q, out);
}